// round 14
// baseline (speedup 1.0000x reference)
#include <cuda_runtime.h>

// SMorph: out = sum_k (x_p+f_k) e^{a(x_p+f_k)} / sum_k e^{a(x_p+f_k)}
// Factored: G=exp(a*x), H=x*G, E_k=exp(a*f_k), F_k=f_k*E_k
//   num = Sum E*H + F*G;  den = Sum E*G
// Packed f32x2, ZERO pack movs: smem plane pre-packed {h,g} (LDS.64),
// taps pre-packed float4 {E,E,0,F} (one LDS.128 broadcast):
//   accA{SumEh, den} += {E,E}*{h,g};  accB{., SumFg} += {0,F}*{h,g}
// -> 2 fma slots per tap-output (vs 3 scalar).
// Y-register-reuse: thread owns 3x2 outputs; its 8 input rows are loaded
// once each and feed both output rows.
// Pitch P2=60: 2*P2 mod 16 = 8 -> each 16-lane LDS.64 phase covers 16
// distinct pair-banks (conflict-free) for warp = 8 lanes x 4 row-pairs.

namespace {
constexpr int BATCH = 8;
constexpr int HH = 192, WW = 192;
constexpr int CO = 8;
constexpr int KH = 7, KW = 7;
constexpr int HO = 186, WO = 186;

constexpr int TILE_X = 48;           // 2 warp-cols * 8 lanes * OPT
constexpr int TILE_Y = 32;           // 4 warp-rows * 4 row-pairs * 2
constexpr int ITX = TILE_X + KW - 1; // 54
constexpr int ITY = TILE_Y + KH - 1; // 38
constexpr int P2  = 60;              // float2 pitch (pairs)
constexpr int OPT = 3;               // outputs per thread in x
constexpr int WINW = OPT + KW - 1;   // 9
}

__device__ __forceinline__ void vfma(unsigned long long& acc,
                                     unsigned long long a,
                                     unsigned long long b) {
    asm("fma.rn.f32x2 %0, %1, %2, %0;" : "+l"(acc) : "l"(a), "l"(b));
}

__global__ __launch_bounds__(256, 4)
void smorph_kernel(const float* __restrict__ x,
                   const float* __restrict__ filt,
                   const float* __restrict__ alpha,
                   float* __restrict__ out)
{
    __shared__ float2 sW[ITY * P2];   // {h, g} packed
    __shared__ float4 sTap[KH * KW];  // {E, E, 0, F}

    const int bc  = blockIdx.z;       // b*8 + c
    const int c   = bc & 7;
    const int tid = threadIdx.x;

    const float a = alpha[c];

    if (tid < KH * KW) {
        float f = filt[c * (KH * KW) + tid];
        float e = __expf(a * f);
        sTap[tid] = make_float4(e, e, 0.0f, f * e);
    }

    const int gx0 = blockIdx.x * TILE_X;
    const int gy0 = blockIdx.y * TILE_Y;
    const float* xb = x + (bc >> 3) * (HH * WW);

    // Cooperative tile fill: {h,g} = {x*exp(a*x), exp(a*x)}
    for (int i = tid; i < ITY * ITX; i += 256) {
        int iy = i / ITX;
        int ix = i - iy * ITX;
        int gy = gy0 + iy;
        int gx = gx0 + ix;
        float v = (gy < HH && gx < WW) ? xb[gy * WW + gx] : 0.0f;
        float g = __expf(a * v);
        sW[iy * P2 + ix] = make_float2(v * g, g);
    }
    __syncthreads();

    // Warp = 8 lanes (x) x 4 row-pairs (y); thread owns 3 cols x 2 rows.
    const int lane = tid & 31;
    const int warp = tid >> 5;        // 0..7
    const int tx = lane & 7;          // 0..7
    const int sy = lane >> 3;         // 0..3
    const int wx = warp & 1;          // 0..1
    const int wy = warp >> 1;         // 0..3
    const int lx = (wx * 8 + tx) * OPT;   // 0..45
    const int ly = (wy * 4 + sy) * 2;     // 0,2,..,30

    unsigned long long accA[2][OPT];  // {Sum E*h, den}
    unsigned long long accB[2][OPT];  // {junk,   Sum F*g}
    #pragma unroll
    for (int r = 0; r < 2; r++)
        #pragma unroll
        for (int o = 0; o < OPT; o++) { accA[r][o] = 0ull; accB[r][o] = 0ull; }

    // 8 input rows of this thread's footprint: load once, feed both out rows.
    #pragma unroll
    for (int r = 0; r < KH + 1; r++) {
        const unsigned long long* rp =
            reinterpret_cast<const unsigned long long*>(&sW[(ly + r) * P2 + lx]);
        unsigned long long w[WINW];
        #pragma unroll
        for (int j = 0; j < WINW; j++) w[j] = rp[j];   // LDS.64, conflict-free

        if (r <= KH - 1) {            // out-row 0, tap row r
            const ulonglong2* tp =
                reinterpret_cast<const ulonglong2*>(&sTap[r * KW]);
            #pragma unroll
            for (int kx = 0; kx < KW; kx++) {
                const ulonglong2 t = tp[kx];   // LDS.128 broadcast
                #pragma unroll
                for (int o = 0; o < OPT; o++) {
                    vfma(accA[0][o], t.x, w[kx + o]);
                    vfma(accB[0][o], t.y, w[kx + o]);
                }
            }
        }
        if (r >= 1) {                 // out-row 1, tap row r-1
            const ulonglong2* tp =
                reinterpret_cast<const ulonglong2*>(&sTap[(r - 1) * KW]);
            #pragma unroll
            for (int kx = 0; kx < KW; kx++) {
                const ulonglong2 t = tp[kx];
                #pragma unroll
                for (int o = 0; o < OPT; o++) {
                    vfma(accA[1][o], t.x, w[kx + o]);
                    vfma(accB[1][o], t.y, w[kx + o]);
                }
            }
        }
    }

    const int ox = gx0 + lx;
    #pragma unroll
    for (int r = 0; r < 2; r++) {
        const int oy = gy0 + ly + r;
        if (oy < HO) {
            float* orow = out + ((long)bc * HO + oy) * WO;
            #pragma unroll
            for (int o = 0; o < OPT; o++) {
                float sEh, den, z, sFg;
                asm("mov.b64 {%0, %1}, %2;" : "=f"(sEh), "=f"(den) : "l"(accA[r][o]));
                asm("mov.b64 {%0, %1}, %2;" : "=f"(z),   "=f"(sFg) : "l"(accB[r][o]));
                if (ox + o < WO)
                    orow[ox + o] = __fdividef(sEh + sFg, den);
            }
        }
    }
}

extern "C" void kernel_launch(void* const* d_in, const int* in_sizes, int n_in,
                              void* d_out, int out_size) {
    const float* x     = (const float*)d_in[0];   // (8,1,192,192)
    const float* filt  = (const float*)d_in[1];   // (8,1,7,7)
    const float* alpha = (const float*)d_in[2];   // (8,1)
    float* out = (float*)d_out;                   // (8,8,186,186)

    dim3 block(256);
    dim3 grid((WO + TILE_X - 1) / TILE_X,   // 4
              (HO + TILE_Y - 1) / TILE_Y,   // 6
              BATCH * CO);                  // 64
    smorph_kernel<<<grid, block>>>(x, filt, alpha, out);
}

// round 15
// speedup vs baseline: 5.1605x; 5.1605x over previous
#include <cuda_runtime.h>

// SMorph: out = sum_k (x_p+f_k) e^{a(x_p+f_k)} / sum_k e^{a(x_p+f_k)}
// Factored: G=exp(a*x), H=x*G, E_k=exp(a*f_k), F_k=f_k*E_k
//   num = sum_k E_k*H + F_k*G;  den = sum_k E_k*G
// Proven R12 scalar structure (y-register-reuse, 4x2 patch/thread,
// conflict-free LDS.32 vs PITCH=71), re-granulated for occupancy:
// 128-thread CTAs on 64x16 tiles -> 8 CTAs/SM, 2304 blocks, smoother
// waves and fill/compute overlap across CTAs.

namespace {
constexpr int BATCH = 8;
constexpr int HH = 192, WW = 192;
constexpr int CO = 8;
constexpr int KH = 7, KW = 7;
constexpr int HO = 186, WO = 186;

constexpr int NT = 128;              // threads per block
constexpr int TILE_X = 64;
constexpr int TILE_Y = 16;           // 2 rows per thread
constexpr int ITX = TILE_X + KW - 1; // 70
constexpr int ITY = TILE_Y + KH - 1; // 22
constexpr int PITCH = 71;
constexpr int OPT = 4;               // outputs per thread in x
constexpr int WINW = OPT + KW - 1;   // 10
}

__global__ __launch_bounds__(NT, 8)
void smorph_kernel(const float* __restrict__ x,
                   const float* __restrict__ filt,
                   const float* __restrict__ alpha,
                   float* __restrict__ out)
{
    __shared__ float sG[ITY * PITCH];
    __shared__ float sH[ITY * PITCH];
    __shared__ float2 sEF[KH * KW];   // {E, F} per tap

    const int bc  = blockIdx.z;       // b*8 + c
    const int c   = bc & 7;
    const int tid = threadIdx.x;

    const float a = alpha[c];

    if (tid < KH * KW) {
        float f = filt[c * (KH * KW) + tid];
        float e = __expf(a * f);
        sEF[tid] = make_float2(e, f * e);
    }

    const int gx0 = blockIdx.x * TILE_X;
    const int gy0 = blockIdx.y * TILE_Y;
    const float* xb = x + (bc >> 3) * (HH * WW);

    // Cooperative tile fill: G = exp(a*x), H = x*G
    for (int i = tid; i < ITY * ITX; i += NT) {
        int iy = i / ITX;
        int ix = i - iy * ITX;
        int gy = gy0 + iy;
        int gx = gx0 + ix;
        float v = (gy < HH && gx < WW) ? xb[gy * WW + gx] : 0.0f;
        float g = __expf(a * v);
        sG[iy * PITCH + ix] = g;
        sH[iy * PITCH + ix] = v * g;
    }
    __syncthreads();

    // Warp geometry: 8 lanes (x) x 4 row-pairs (y); thread owns 4x2 patch.
    const int lane = tid & 31;
    const int warp = tid >> 5;        // 0..3
    const int tx = lane & 7;          // 0..7
    const int sy = lane >> 3;         // 0..3
    const int wx = warp & 1;          // 0..1
    const int wy = warp >> 1;         // 0..1
    const int lx = (wx * 8 + tx) * OPT;     // 0..60
    const int ly = (wy * 4 + sy) * 2;       // 0,2,..,14 (first output row)

    float accN[2][OPT], accD[2][OPT];
    #pragma unroll
    for (int r = 0; r < 2; r++)
        #pragma unroll
        for (int o = 0; o < OPT; o++) { accN[r][o] = 0.f; accD[r][o] = 0.f; }

    // 8 input rows of this thread's footprint: load once, feed both out rows.
    #pragma unroll
    for (int r = 0; r < KH + 1; r++) {
        const float* gr = &sG[(ly + r) * PITCH + lx];
        const float* hr = &sH[(ly + r) * PITCH + lx];
        float g[WINW], h[WINW];
        #pragma unroll
        for (int j = 0; j < WINW; j++) {
            g[j] = gr[j];
            h[j] = hr[j];
        }

        // out-row 0 uses tap row r (valid for r = 0..6)
        if (r <= KH - 1) {
            #pragma unroll
            for (int kx = 0; kx < KW; kx++) {
                const float2 ef = sEF[r * KW + kx];   // broadcast
                const float E = ef.x, F = ef.y;
                #pragma unroll
                for (int o = 0; o < OPT; o++) {
                    accN[0][o] = fmaf(E, h[kx + o], fmaf(F, g[kx + o], accN[0][o]));
                    accD[0][o] = fmaf(E, g[kx + o], accD[0][o]);
                }
            }
        }
        // out-row 1 uses tap row r-1 (valid for r = 1..7)
        if (r >= 1) {
            #pragma unroll
            for (int kx = 0; kx < KW; kx++) {
                const float2 ef = sEF[(r - 1) * KW + kx];   // broadcast
                const float E = ef.x, F = ef.y;
                #pragma unroll
                for (int o = 0; o < OPT; o++) {
                    accN[1][o] = fmaf(E, h[kx + o], fmaf(F, g[kx + o], accN[1][o]));
                    accD[1][o] = fmaf(E, g[kx + o], accD[1][o]);
                }
            }
        }
    }

    const int ox = gx0 + lx;
    #pragma unroll
    for (int r = 0; r < 2; r++) {
        const int oy = gy0 + ly + r;
        if (oy < HO) {
            float* orow = out + ((long)bc * HO + oy) * WO;
            float v0 = __fdividef(accN[r][0], accD[r][0]);
            float v1 = __fdividef(accN[r][1], accD[r][1]);
            float v2 = __fdividef(accN[r][2], accD[r][2]);
            float v3 = __fdividef(accN[r][3], accD[r][3]);
            if (ox + 3 < WO) {
                // row base 8B-aligned (WO even), not 16B for odd oy: 2x STG.64
                *reinterpret_cast<float2*>(orow + ox)     = make_float2(v0, v1);
                *reinterpret_cast<float2*>(orow + ox + 2) = make_float2(v2, v3);
            } else {
                if (ox + 0 < WO) orow[ox + 0] = v0;
                if (ox + 1 < WO) orow[ox + 1] = v1;
                if (ox + 2 < WO) orow[ox + 2] = v2;
                if (ox + 3 < WO) orow[ox + 3] = v3;
            }
        }
    }
}

extern "C" void kernel_launch(void* const* d_in, const int* in_sizes, int n_in,
                              void* d_out, int out_size) {
    const float* x     = (const float*)d_in[0];   // (8,1,192,192)
    const float* filt  = (const float*)d_in[1];   // (8,1,7,7)
    const float* alpha = (const float*)d_in[2];   // (8,1)
    float* out = (float*)d_out;                   // (8,8,186,186)

    dim3 block(NT);
    dim3 grid((WO + TILE_X - 1) / TILE_X,   // 3
              (HO + TILE_Y - 1) / TILE_Y,   // 12
              BATCH * CO);                  // 64
    smorph_kernel<<<grid, block>>>(x, filt, alpha, out);
}

// round 16
// speedup vs baseline: 5.1737x; 1.0026x over previous
#include <cuda_runtime.h>

// SMorph: out = sum_k (x_p+f_k) e^{a(x_p+f_k)} / sum_k e^{a(x_p+f_k)}
// Factored: G=exp(a*x), H=x*G, E_k=exp(a*f_k), F_k=f_k*E_k
//   num = sum_k E_k*H + F_k*G;  den = sum_k E_k*G
// R15 scalar structure (y-register-reuse, 4x2 patch/thread) with pitch 72:
// window loads become float2 LDS.64 (5+5 per row instead of 10+10 LDS.32),
// halving window issue slots. Pair-bank check (warp = 8 lanes x 4 row-pairs):
// pair-bank = 36*row + lx/2 + j mod 16; a 16-lane phase spans {2tx + 8sy} =
// 16 distinct pair-banks -> conflict-free, L1 wavefronts unchanged.

namespace {
constexpr int BATCH = 8;
constexpr int HH = 192, WW = 192;
constexpr int CO = 8;
constexpr int KH = 7, KW = 7;
constexpr int HO = 186, WO = 186;

constexpr int NT = 128;              // threads per block
constexpr int TILE_X = 64;
constexpr int TILE_Y = 16;           // 2 rows per thread
constexpr int ITX = TILE_X + KW - 1; // 70
constexpr int ITY = TILE_Y + KH - 1; // 22
constexpr int PITCH = 72;            // even pitch: enables 8B-aligned LDS.64
constexpr int OPT = 4;               // outputs per thread in x
constexpr int WINW = OPT + KW - 1;   // 10
}

__global__ __launch_bounds__(NT, 8)
void smorph_kernel(const float* __restrict__ x,
                   const float* __restrict__ filt,
                   const float* __restrict__ alpha,
                   float* __restrict__ out)
{
    __shared__ float sG[ITY * PITCH];
    __shared__ float sH[ITY * PITCH];
    __shared__ float2 sEF[KH * KW];   // {E, F} per tap

    const int bc  = blockIdx.z;       // b*8 + c
    const int c   = bc & 7;
    const int tid = threadIdx.x;

    const float a = alpha[c];

    if (tid < KH * KW) {
        float f = filt[c * (KH * KW) + tid];
        float e = __expf(a * f);
        sEF[tid] = make_float2(e, f * e);
    }

    const int gx0 = blockIdx.x * TILE_X;
    const int gy0 = blockIdx.y * TILE_Y;
    const float* xb = x + (bc >> 3) * (HH * WW);

    // Cooperative tile fill: G = exp(a*x), H = x*G
    for (int i = tid; i < ITY * ITX; i += NT) {
        int iy = i / ITX;
        int ix = i - iy * ITX;
        int gy = gy0 + iy;
        int gx = gx0 + ix;
        float v = (gy < HH && gx < WW) ? xb[gy * WW + gx] : 0.0f;
        float g = __expf(a * v);
        sG[iy * PITCH + ix] = g;
        sH[iy * PITCH + ix] = v * g;
    }
    __syncthreads();

    // Warp geometry: 8 lanes (x) x 4 row-pairs (y); thread owns 4x2 patch.
    const int lane = tid & 31;
    const int warp = tid >> 5;        // 0..3
    const int tx = lane & 7;          // 0..7
    const int sy = lane >> 3;         // 0..3
    const int wx = warp & 1;          // 0..1
    const int wy = warp >> 1;         // 0..1
    const int lx = (wx * 8 + tx) * OPT;     // 0..60, multiple of 4
    const int ly = (wy * 4 + sy) * 2;       // 0,2,..,14 (first output row)

    float accN[2][OPT], accD[2][OPT];
    #pragma unroll
    for (int r = 0; r < 2; r++)
        #pragma unroll
        for (int o = 0; o < OPT; o++) { accN[r][o] = 0.f; accD[r][o] = 0.f; }

    // 8 input rows of this thread's footprint: load once, feed both out rows.
    #pragma unroll
    for (int r = 0; r < KH + 1; r++) {
        const float2* gr2 = reinterpret_cast<const float2*>(&sG[(ly + r) * PITCH + lx]);
        const float2* hr2 = reinterpret_cast<const float2*>(&sH[(ly + r) * PITCH + lx]);
        float g[WINW], h[WINW];
        #pragma unroll
        for (int j = 0; j < WINW / 2; j++) {
            float2 gp = gr2[j];                   // LDS.64, conflict-free
            float2 hp = hr2[j];                   // LDS.64, conflict-free
            g[2 * j]     = gp.x;
            g[2 * j + 1] = gp.y;
            h[2 * j]     = hp.x;
            h[2 * j + 1] = hp.y;
        }

        // out-row 0 uses tap row r (valid for r = 0..6)
        if (r <= KH - 1) {
            #pragma unroll
            for (int kx = 0; kx < KW; kx++) {
                const float2 ef = sEF[r * KW + kx];   // LDS.64 broadcast
                const float E = ef.x, F = ef.y;
                #pragma unroll
                for (int o = 0; o < OPT; o++) {
                    accN[0][o] = fmaf(E, h[kx + o], fmaf(F, g[kx + o], accN[0][o]));
                    accD[0][o] = fmaf(E, g[kx + o], accD[0][o]);
                }
            }
        }
        // out-row 1 uses tap row r-1 (valid for r = 1..7)
        if (r >= 1) {
            #pragma unroll
            for (int kx = 0; kx < KW; kx++) {
                const float2 ef = sEF[(r - 1) * KW + kx];   // LDS.64 broadcast
                const float E = ef.x, F = ef.y;
                #pragma unroll
                for (int o = 0; o < OPT; o++) {
                    accN[1][o] = fmaf(E, h[kx + o], fmaf(F, g[kx + o], accN[1][o]));
                    accD[1][o] = fmaf(E, g[kx + o], accD[1][o]);
                }
            }
        }
    }

    const int ox = gx0 + lx;
    #pragma unroll
    for (int r = 0; r < 2; r++) {
        const int oy = gy0 + ly + r;
        if (oy < HO) {
            float* orow = out + ((long)bc * HO + oy) * WO;
            float v0 = __fdividef(accN[r][0], accD[r][0]);
            float v1 = __fdividef(accN[r][1], accD[r][1]);
            float v2 = __fdividef(accN[r][2], accD[r][2]);
            float v3 = __fdividef(accN[r][3], accD[r][3]);
            if (ox + 3 < WO) {
                // row base 8B-aligned (WO even), not 16B for odd oy: 2x STG.64
                *reinterpret_cast<float2*>(orow + ox)     = make_float2(v0, v1);
                *reinterpret_cast<float2*>(orow + ox + 2) = make_float2(v2, v3);
            } else {
                if (ox + 0 < WO) orow[ox + 0] = v0;
                if (ox + 1 < WO) orow[ox + 1] = v1;
                if (ox + 2 < WO) orow[ox + 2] = v2;
                if (ox + 3 < WO) orow[ox + 3] = v3;
            }
        }
    }
}

extern "C" void kernel_launch(void* const* d_in, const int* in_sizes, int n_in,
                              void* d_out, int out_size) {
    const float* x     = (const float*)d_in[0];   // (8,1,192,192)
    const float* filt  = (const float*)d_in[1];   // (8,1,7,7)
    const float* alpha = (const float*)d_in[2];   // (8,1)
    float* out = (float*)d_out;                   // (8,8,186,186)

    dim3 block(NT);
    dim3 grid((WO + TILE_X - 1) / TILE_X,   // 3
              (HO + TILE_Y - 1) / TILE_Y,   // 12
              BATCH * CO);                  // 64
    smorph_kernel<<<grid, block>>>(x, filt, alpha, out);
}